// round 2
// baseline (speedup 1.0000x reference)
#include <cuda_runtime.h>
#include <math.h>

#define B    16
#define CIN  512
#define COUT 512
#define H    32
#define YW   66            // row stride of y (65 valid cols + 1 pad)
#define YPLANE (65*66)     // 65 rows

// ---------------- device scratch (static, no allocation) ----------------
__device__ float g_style[B*CIN];                 // 32 KB
__device__ float g_dcoef[B*COUT];                // 32 KB
__device__ float g_wsq[COUT*CIN];                // 1 MB
__device__ float g_wT[CIN*9*COUT];               // 9.4 MB   [ci][tap][co]
__device__ float g_xm[B*CIN*H*H];                // 33.5 MB  modulated x
__device__ float g_y[(size_t)B*COUT*YPLANE];     // 140.6 MB transposed-conv output (pre-FIR, pre-demod)

// ---------------- K1: style = w_latent @ (A/sqrt(512)).T + bias ----------------
__global__ void k_style(const float* __restrict__ wl, const float* __restrict__ aw,
                        const float* __restrict__ ab) {
    int w = blockIdx.x * 8 + (threadIdx.x >> 5);   // 8192 warps total
    int lane = threadIdx.x & 31;
    int b = w >> 9, ci = w & 511;
    const float* wlp = wl + b * 512;
    const float* awp = aw + (size_t)ci * 512;
    float s = 0.f;
    #pragma unroll 4
    for (int k = lane; k < 512; k += 32) s += wlp[k] * awp[k];
    #pragma unroll
    for (int o = 16; o; o >>= 1) s += __shfl_down_sync(0xffffffffu, s, o);
    if (lane == 0) g_style[w] = s * 0.04419417382415922f + ab[ci];  // 1/sqrt(512)
}

// ---------------- K2: wsq[co][ci] = sum_k w^2 ----------------
__global__ void k_wsq(const float* __restrict__ cw) {
    int i = blockIdx.x * 256 + threadIdx.x;      // co*512+ci
    if (i < COUT * CIN) {
        const float* p = cw + (size_t)i * 9;
        float s = 0.f;
        #pragma unroll
        for (int t = 0; t < 9; t++) s += p[t] * p[t];
        g_wsq[i] = s;
    }
}

// ---------------- K3: dcoef[b][co] = rsqrt(sum_ci wsq*style^2 + 1e-8) ----------------
__global__ void k_dcoef() {
    int w = blockIdx.x * 8 + (threadIdx.x >> 5);
    int lane = threadIdx.x & 31;
    int b = w >> 9, co = w & 511;
    float s = 0.f;
    #pragma unroll 4
    for (int ci = lane; ci < 512; ci += 32) {
        float st = g_style[b * 512 + ci];
        s += g_wsq[co * 512 + ci] * st * st;
    }
    #pragma unroll
    for (int o = 16; o; o >>= 1) s += __shfl_down_sync(0xffffffffu, s, o);
    if (lane == 0) g_dcoef[w] = rsqrtf(s + 1e-8f);
}

// ---------------- K4: xm = x * style (modulate input instead of weights) ----------------
__global__ void k_modx(const float* __restrict__ x) {
    int i = blockIdx.x * 256 + threadIdx.x;
    if (i < B * CIN * H * H) g_xm[i] = x[i] * g_style[i >> 10];   // 1024 px / channel
}

// ---------------- K5: wT[ci][tap][co] = conv_weight[co][ci][tap] ----------------
__global__ void k_wt(const float* __restrict__ cw) {
    int i = blockIdx.x * 256 + threadIdx.x;
    if (i < CIN * 9 * COUT) {
        int co  = i & 511;
        int tap = (i >> 9) % 9;
        int ci  = i / (9 * 512);
        g_wT[i] = cw[((size_t)co * 512 + ci) * 9 + tap];
    }
}

// ---------------- K6: sparse transposed conv (the hot kernel) ----------------
// y[2m+pu, 2n+pv] per cell (m,n): 9 FMAs covering all 4 parities.
//   y[2m  ,2n  ] += x11*w0 + x10*w2 + x01*w6 + x00*w8
//   y[2m  ,2n+1] += x11*w1 + x01*w7
//   y[2m+1,2n  ] += x11*w3 + x10*w5
//   y[2m+1,2n+1] += x11*w4
// where x11=x[m,n], x10=x[m,n-1], x01=x[m-1,n], x00=x[m-1,n-1]; cells m,n in [0,32].
__global__ void __launch_bounds__(256) k_conv() {
    const int tile = blockIdx.x;                 // 0..24 (5x5 over 33x33 cells)
    const int m0 = (tile / 5) * 8;
    const int n0 = (tile % 5) * 8;
    const int co0 = blockIdx.y * 32;
    const int b  = blockIdx.z;
    const int tid = threadIdx.x;

    __shared__ float xs[8][9][10];               // 8 ci x 9x9 x-halo (+pad)
    __shared__ float ws[8][9][32];               // 8 ci x 9 taps x 32 co

    const int cs     = tid & 15;                 // spatial: 4x4 grid of 2x2 cell blocks
    const int co_sub = tid >> 4;                 // 16 co groups (each owns co_sub, co_sub+16)
    const int cm0 = (cs >> 2) << 1;
    const int cn0 = (cs & 3) << 1;

    float acc[2][2][2][4];
    #pragma unroll
    for (int a = 0; a < 2; a++)
        #pragma unroll
        for (int i = 0; i < 2; i++)
            #pragma unroll
            for (int j = 0; j < 2; j++)
                #pragma unroll
                for (int p = 0; p < 4; p++) acc[a][i][j][p] = 0.f;

    const float* xm_b = g_xm + (size_t)b * (CIN * H * H);

    for (int ci0 = 0; ci0 < CIN; ci0 += 8) {
        __syncthreads();
        for (int e = tid; e < 8 * 81; e += 256) {
            int ci_l = e / 81; int rr = e - ci_l * 81; int r = rr / 9; int c = rr - r * 9;
            int gm = m0 - 1 + r, gn = n0 - 1 + c;
            float v = 0.f;
            if ((unsigned)gm < 32u && (unsigned)gn < 32u)
                v = xm_b[(ci0 + ci_l) * 1024 + gm * 32 + gn];
            xs[ci_l][r][c] = v;
        }
        for (int e = tid; e < 8 * 288; e += 256) {
            int ci_l = e / 288; int rest = e - ci_l * 288;
            int tap = rest >> 5; int co_l = rest & 31;
            ws[ci_l][tap][co_l] = g_wT[(size_t)((ci0 + ci_l) * 9 + tap) * 512 + co0 + co_l];
        }
        __syncthreads();
        #pragma unroll
        for (int ci_l = 0; ci_l < 8; ci_l++) {
            float xv[3][3];
            #pragma unroll
            for (int r = 0; r < 3; r++)
                #pragma unroll
                for (int c = 0; c < 3; c++) xv[r][c] = xs[ci_l][cm0 + r][cn0 + c];
            #pragma unroll
            for (int ck = 0; ck < 2; ck++) {
                float wv[9];
                #pragma unroll
                for (int t = 0; t < 9; t++) wv[t] = ws[ci_l][t][co_sub + (ck << 4)];
                #pragma unroll
                for (int i = 0; i < 2; i++)
                    #pragma unroll
                    for (int j = 0; j < 2; j++) {
                        float x00 = xv[i][j],     x01 = xv[i][j + 1];
                        float x10 = xv[i + 1][j], x11 = xv[i + 1][j + 1];
                        float* a = acc[ck][i][j];
                        a[0] = fmaf(x11, wv[0], a[0]);
                        a[0] = fmaf(x10, wv[2], a[0]);
                        a[0] = fmaf(x01, wv[6], a[0]);
                        a[0] = fmaf(x00, wv[8], a[0]);
                        a[1] = fmaf(x11, wv[1], a[1]);
                        a[1] = fmaf(x01, wv[7], a[1]);
                        a[2] = fmaf(x11, wv[3], a[2]);
                        a[2] = fmaf(x10, wv[5], a[2]);
                        a[3] = fmaf(x11, wv[4], a[3]);
                    }
            }
        }
    }
    #pragma unroll
    for (int ck = 0; ck < 2; ck++) {
        int co = co0 + co_sub + (ck << 4);
        float* yp = g_y + (size_t)(b * COUT + co) * YPLANE;
        #pragma unroll
        for (int i = 0; i < 2; i++)
            #pragma unroll
            for (int j = 0; j < 2; j++) {
                int m = m0 + cm0 + i, n = n0 + cn0 + j;
                if (m <= 32 && n <= 32) {
                    const float* a = acc[ck][i][j];
                    yp[(2 * m) * YW + 2 * n] = a[0];
                    if (n < 32) yp[(2 * m) * YW + 2 * n + 1] = a[1];
                    if (m < 32) yp[(2 * m + 1) * YW + 2 * n] = a[2];
                    if (m < 32 && n < 32) yp[(2 * m + 1) * YW + 2 * n + 1] = a[3];
                }
            }
    }
}

// ---------------- K7: FIR (4x4 [1,3,3,1]^2/16) + demod + noise + bias + lrelu + clamp ----------------
__global__ void __launch_bounds__(256) k_fir(const float* __restrict__ noise,
                                             const float* __restrict__ nstr,
                                             const float* __restrict__ bias,
                                             float* __restrict__ out) {
    const int rg = blockIdx.x;       // 16 groups of 4 output rows
    const int co = blockIdx.y;
    const int b  = blockIdx.z;
    const int tid = threadIdx.x;
    const int r  = tid >> 6;         // 0..3
    const int vq = tid & 63;
    const int u0 = rg * 4;

    __shared__ float ys[7][68];
    const float* yp = g_y + (size_t)(b * COUT + co) * YPLANE;
    for (int e = tid; e < 7 * 68; e += 256) {
        int rr = e / 68, cc = e - rr * 68;
        int u = u0 - 1 + rr, v = cc - 1;
        ys[rr][cc] = ((unsigned)u <= 64u && (unsigned)v <= 64u) ? yp[u * YW + v] : 0.f;
    }
    __syncthreads();

    const float f[4] = {0.25f, 0.75f, 0.75f, 0.25f};   // outer product = [1,3,3,1]^2 / 16
    float accum = 0.f;
    #pragma unroll
    for (int a = 0; a < 4; a++) {
        float row = 0.f;
        #pragma unroll
        for (int bb = 0; bb < 4; bb++) row = fmaf(f[bb], ys[r + a][vq + bb], row);
        accum = fmaf(f[a], row, accum);
    }
    int u = u0 + r;
    float val = accum * g_dcoef[b * 512 + co];
    val = fmaf(noise[(b << 12) + u * 64 + vq], nstr[0], val);
    val += bias[co];
    val = (val > 0.f ? val : 0.2f * val) * 1.4142135623730951f;   // lrelu gain sqrt(2)
    val = fminf(fmaxf(val, -256.f), 256.f);
    out[(((size_t)b * 512 + co) * 64 + u) * 64 + vq] = val;
}

// ---------------- launch ----------------
extern "C" void kernel_launch(void* const* d_in, const int* in_sizes, int n_in,
                              void* d_out, int out_size) {
    const float* x     = (const float*)d_in[0];
    const float* wl    = (const float*)d_in[1];
    const float* aw    = (const float*)d_in[2];
    const float* ab    = (const float*)d_in[3];
    const float* cw    = (const float*)d_in[4];
    const float* noise = (const float*)d_in[5];
    const float* nstr  = (const float*)d_in[6];
    const float* bias  = (const float*)d_in[7];
    float* out = (float*)d_out;

    k_style<<<1024, 256>>>(wl, aw, ab);
    k_wsq<<<(COUT * CIN + 255) / 256, 256>>>(cw);
    k_dcoef<<<1024, 256>>>();
    k_modx<<<(B * CIN * H * H + 255) / 256, 256>>>(x);
    k_wt<<<(CIN * 9 * COUT + 255) / 256, 256>>>(cw);

    dim3 g6(25, COUT / 32, B);
    k_conv<<<g6, 256>>>();

    dim3 g7(16, COUT, B);
    k_fir<<<g7, 256>>>(noise, nstr, bias, out);
}

// round 3
// speedup vs baseline: 1.0006x; 1.0006x over previous
#include <cuda_runtime.h>
#include <math.h>

#define B    16
#define CIN  512
#define COUT 512
#define H    32
#define YW   66            // row stride of y (65 valid cols + 1 pad)
#define YPLANE (65*66)     // 65 rows

// ---------------- device scratch (static, no allocation) ----------------
__device__ float g_style[B*CIN];                 // 32 KB
__device__ float g_dcoef[B*COUT];                // 32 KB
__device__ float g_wsq[COUT*CIN];                // 1 MB
__device__ float g_wT[CIN*9*COUT];               // 9.4 MB   [ci][tap][co]
__device__ float g_xm[B*CIN*H*H];                // 33.5 MB  modulated x
__device__ float g_y[(size_t)B*COUT*YPLANE];     // 140.6 MB transposed-conv output (pre-FIR, pre-demod)

// ---------------- K1: style = w_latent @ (A/sqrt(512)).T + bias ----------------
__global__ void k_style(const float* __restrict__ wl, const float* __restrict__ aw,
                        const float* __restrict__ ab) {
    int w = blockIdx.x * 8 + (threadIdx.x >> 5);   // 8192 warps total
    int lane = threadIdx.x & 31;
    int b = w >> 9, ci = w & 511;
    const float* wlp = wl + b * 512;
    const float* awp = aw + (size_t)ci * 512;
    float s = 0.f;
    #pragma unroll 4
    for (int k = lane; k < 512; k += 32) s += wlp[k] * awp[k];
    #pragma unroll
    for (int o = 16; o; o >>= 1) s += __shfl_down_sync(0xffffffffu, s, o);
    if (lane == 0) g_style[w] = s * 0.04419417382415922f + ab[ci];  // 1/sqrt(512)
}

// ---------------- K2: wsq[co][ci] = sum_k w^2 ----------------
__global__ void k_wsq(const float* __restrict__ cw) {
    int i = blockIdx.x * 256 + threadIdx.x;      // co*512+ci
    if (i < COUT * CIN) {
        const float* p = cw + (size_t)i * 9;
        float s = 0.f;
        #pragma unroll
        for (int t = 0; t < 9; t++) s += p[t] * p[t];
        g_wsq[i] = s;
    }
}

// ---------------- K3: dcoef[b][co] = rsqrt(sum_ci wsq*style^2 + 1e-8) ----------------
__global__ void k_dcoef() {
    int w = blockIdx.x * 8 + (threadIdx.x >> 5);
    int lane = threadIdx.x & 31;
    int b = w >> 9, co = w & 511;
    float s = 0.f;
    #pragma unroll 4
    for (int ci = lane; ci < 512; ci += 32) {
        float st = g_style[b * 512 + ci];
        s += g_wsq[co * 512 + ci] * st * st;
    }
    #pragma unroll
    for (int o = 16; o; o >>= 1) s += __shfl_down_sync(0xffffffffu, s, o);
    if (lane == 0) g_dcoef[w] = rsqrtf(s + 1e-8f);
}

// ---------------- K4: xm = x * style (modulate input instead of weights) ----------------
__global__ void k_modx(const float* __restrict__ x) {
    int i = blockIdx.x * 256 + threadIdx.x;
    if (i < B * CIN * H * H) g_xm[i] = x[i] * g_style[i >> 10];   // 1024 px / channel
}

// ---------------- K5: wT[ci][tap][co] = conv_weight[co][ci][tap] ----------------
__global__ void k_wt(const float* __restrict__ cw) {
    int i = blockIdx.x * 256 + threadIdx.x;
    if (i < CIN * 9 * COUT) {
        int co  = i & 511;
        int tap = (i >> 9) % 9;
        int ci  = i / (9 * 512);
        g_wT[i] = cw[((size_t)co * 512 + ci) * 9 + tap];
    }
}

// ---------------- K6: sparse transposed conv (the hot kernel) ----------------
// y[2m+pu, 2n+pv] per cell (m,n): 9 FMAs covering all 4 parities.
//   y[2m  ,2n  ] += x11*w0 + x10*w2 + x01*w6 + x00*w8
//   y[2m  ,2n+1] += x11*w1 + x01*w7
//   y[2m+1,2n  ] += x11*w3 + x10*w5
//   y[2m+1,2n+1] += x11*w4
// where x11=x[m,n], x10=x[m,n-1], x01=x[m-1,n], x00=x[m-1,n-1]; cells m,n in [0,32].
__global__ void __launch_bounds__(256) k_conv() {
    const int tile = blockIdx.x;                 // 0..24 (5x5 over 33x33 cells)
    const int m0 = (tile / 5) * 8;
    const int n0 = (tile % 5) * 8;
    const int co0 = blockIdx.y * 32;
    const int b  = blockIdx.z;
    const int tid = threadIdx.x;

    __shared__ float xs[8][9][10];               // 8 ci x 9x9 x-halo (+pad)
    __shared__ float ws[8][9][32];               // 8 ci x 9 taps x 32 co

    const int cs     = tid & 15;                 // spatial: 4x4 grid of 2x2 cell blocks
    const int co_sub = tid >> 4;                 // 16 co groups (each owns co_sub, co_sub+16)
    const int cm0 = (cs >> 2) << 1;
    const int cn0 = (cs & 3) << 1;

    float acc[2][2][2][4];
    #pragma unroll
    for (int a = 0; a < 2; a++)
        #pragma unroll
        for (int i = 0; i < 2; i++)
            #pragma unroll
            for (int j = 0; j < 2; j++)
                #pragma unroll
                for (int p = 0; p < 4; p++) acc[a][i][j][p] = 0.f;

    const float* xm_b = g_xm + (size_t)b * (CIN * H * H);

    for (int ci0 = 0; ci0 < CIN; ci0 += 8) {
        __syncthreads();
        for (int e = tid; e < 8 * 81; e += 256) {
            int ci_l = e / 81; int rr = e - ci_l * 81; int r = rr / 9; int c = rr - r * 9;
            int gm = m0 - 1 + r, gn = n0 - 1 + c;
            float v = 0.f;
            if ((unsigned)gm < 32u && (unsigned)gn < 32u)
                v = xm_b[(ci0 + ci_l) * 1024 + gm * 32 + gn];
            xs[ci_l][r][c] = v;
        }
        for (int e = tid; e < 8 * 288; e += 256) {
            int ci_l = e / 288; int rest = e - ci_l * 288;
            int tap = rest >> 5; int co_l = rest & 31;
            ws[ci_l][tap][co_l] = g_wT[(size_t)((ci0 + ci_l) * 9 + tap) * 512 + co0 + co_l];
        }
        __syncthreads();
        #pragma unroll
        for (int ci_l = 0; ci_l < 8; ci_l++) {
            float xv[3][3];
            #pragma unroll
            for (int r = 0; r < 3; r++)
                #pragma unroll
                for (int c = 0; c < 3; c++) xv[r][c] = xs[ci_l][cm0 + r][cn0 + c];
            #pragma unroll
            for (int ck = 0; ck < 2; ck++) {
                float wv[9];
                #pragma unroll
                for (int t = 0; t < 9; t++) wv[t] = ws[ci_l][t][co_sub + (ck << 4)];
                #pragma unroll
                for (int i = 0; i < 2; i++)
                    #pragma unroll
                    for (int j = 0; j < 2; j++) {
                        float x00 = xv[i][j],     x01 = xv[i][j + 1];
                        float x10 = xv[i + 1][j], x11 = xv[i + 1][j + 1];
                        float* a = acc[ck][i][j];
                        a[0] = fmaf(x11, wv[0], a[0]);
                        a[0] = fmaf(x10, wv[2], a[0]);
                        a[0] = fmaf(x01, wv[6], a[0]);
                        a[0] = fmaf(x00, wv[8], a[0]);
                        a[1] = fmaf(x11, wv[1], a[1]);
                        a[1] = fmaf(x01, wv[7], a[1]);
                        a[2] = fmaf(x11, wv[3], a[2]);
                        a[2] = fmaf(x10, wv[5], a[2]);
                        a[3] = fmaf(x11, wv[4], a[3]);
                    }
            }
        }
    }
    #pragma unroll
    for (int ck = 0; ck < 2; ck++) {
        int co = co0 + co_sub + (ck << 4);
        float* yp = g_y + (size_t)(b * COUT + co) * YPLANE;
        #pragma unroll
        for (int i = 0; i < 2; i++)
            #pragma unroll
            for (int j = 0; j < 2; j++) {
                int m = m0 + cm0 + i, n = n0 + cn0 + j;
                if (m <= 32 && n <= 32) {
                    const float* a = acc[ck][i][j];
                    yp[(2 * m) * YW + 2 * n] = a[0];
                    if (n < 32) yp[(2 * m) * YW + 2 * n + 1] = a[1];
                    if (m < 32) yp[(2 * m + 1) * YW + 2 * n] = a[2];
                    if (m < 32 && n < 32) yp[(2 * m + 1) * YW + 2 * n + 1] = a[3];
                }
            }
    }
}

// ---------------- K7: FIR (4x4 [1,3,3,1]^2/16) + demod + noise + bias + lrelu + clamp ----------------
__global__ void __launch_bounds__(256) k_fir(const float* __restrict__ noise,
                                             const float* __restrict__ nstr,
                                             const float* __restrict__ bias,
                                             float* __restrict__ out) {
    const int rg = blockIdx.x;       // 16 groups of 4 output rows
    const int co = blockIdx.y;
    const int b  = blockIdx.z;
    const int tid = threadIdx.x;
    const int r  = tid >> 6;         // 0..3
    const int vq = tid & 63;
    const int u0 = rg * 4;

    __shared__ float ys[7][68];
    const float* yp = g_y + (size_t)(b * COUT + co) * YPLANE;
    for (int e = tid; e < 7 * 68; e += 256) {
        int rr = e / 68, cc = e - rr * 68;
        int u = u0 - 1 + rr, v = cc - 1;
        ys[rr][cc] = ((unsigned)u <= 64u && (unsigned)v <= 64u) ? yp[u * YW + v] : 0.f;
    }
    __syncthreads();

    const float f[4] = {0.25f, 0.75f, 0.75f, 0.25f};   // outer product = [1,3,3,1]^2 / 16
    float accum = 0.f;
    #pragma unroll
    for (int a = 0; a < 4; a++) {
        float row = 0.f;
        #pragma unroll
        for (int bb = 0; bb < 4; bb++) row = fmaf(f[bb], ys[r + a][vq + bb], row);
        accum = fmaf(f[a], row, accum);
    }
    int u = u0 + r;
    float val = accum * g_dcoef[b * 512 + co];
    val = fmaf(noise[(b << 12) + u * 64 + vq], nstr[0], val);
    val += bias[co];
    val = (val > 0.f ? val : 0.2f * val) * 1.4142135623730951f;   // lrelu gain sqrt(2)
    val = fminf(fmaxf(val, -256.f), 256.f);
    out[(((size_t)b * 512 + co) * 64 + u) * 64 + vq] = val;
}

// ---------------- launch ----------------
extern "C" void kernel_launch(void* const* d_in, const int* in_sizes, int n_in,
                              void* d_out, int out_size) {
    const float* x     = (const float*)d_in[0];
    const float* wl    = (const float*)d_in[1];
    const float* aw    = (const float*)d_in[2];
    const float* ab    = (const float*)d_in[3];
    const float* cw    = (const float*)d_in[4];
    const float* noise = (const float*)d_in[5];
    const float* nstr  = (const float*)d_in[6];
    const float* bias  = (const float*)d_in[7];
    float* out = (float*)d_out;

    k_style<<<1024, 256>>>(wl, aw, ab);
    k_wsq<<<(COUT * CIN + 255) / 256, 256>>>(cw);
    k_dcoef<<<1024, 256>>>();
    k_modx<<<(B * CIN * H * H + 255) / 256, 256>>>(x);
    k_wt<<<(CIN * 9 * COUT + 255) / 256, 256>>>(cw);

    dim3 g6(25, COUT / 32, B);
    k_conv<<<g6, 256>>>();

    dim3 g7(16, COUT, B);
    k_fir<<<g7, 256>>>(noise, nstr, bias, out);
}

// round 5
// speedup vs baseline: 4.6967x; 4.6939x over previous
#include <cuda_runtime.h>
#include <cuda_bf16.h>
#include <cstdint>
#include <math.h>

#define B_    16
#define CIN   512
#define COUT  512
#define NPOSR 18688            // 146*128 padded position rows
#define NQV   18496            // 16*1156 valid positions
#define IDX(p,q) ((size_t)(p)*NQV + (q))

// ------------------------- device scratch -------------------------
__device__ float g_style[B_*CIN];
__device__ float g_wsq[COUT*CIN];
__device__ float g_dcoef[B_*COUT];
__device__ __nv_bfloat16 g_xth[(size_t)B_*1024*512];                  // [b][pix][ci] hi
__device__ __nv_bfloat16 g_xtl[(size_t)B_*1024*512];                  // lo
__device__ __align__(128) __nv_bfloat16 g_Xh[(size_t)4*8*NPOSR*64];   // [shift][chunk][q][64] swizzled
__device__ __align__(128) __nv_bfloat16 g_Xl[(size_t)4*8*NPOSR*64];
__device__ __align__(128) __nv_bfloat16 g_Wh[(size_t)9*8*512*64];     // [tap][chunk][co][64] swizzled
__device__ __align__(128) __nv_bfloat16 g_Wl[(size_t)9*8*512*64];
__device__ __align__(16)  float g_yp[(size_t)4*NQV*512];              // [parity][q][co]

__constant__ int c_taps[4][4] = {{0,2,6,8},{1,7,0,0},{3,5,0,0},{4,0,0,0}};
__constant__ int c_shf [4][4] = {{0,1,2,3},{0,2,0,0},{0,1,0,0},{0,0,0,0}};
__constant__ int c_nkb [4]    = {4,2,2,1};

// ------------------------- helpers -------------------------
__device__ __forceinline__ uint32_t smem_u32(const void* p) {
    uint32_t a;
    asm("{ .reg .u64 t; cvta.to.shared.u64 t, %1; cvt.u32.u64 %0, t; }" : "=r"(a) : "l"(p));
    return a;
}
__device__ __forceinline__ void cp16(uint32_t s, const void* g) {
    asm volatile("cp.async.cg.shared.global [%0], [%1], 16;" :: "r"(s), "l"(g) : "memory");
}
__device__ __forceinline__ void ldsm4(uint32_t& r0, uint32_t& r1, uint32_t& r2, uint32_t& r3,
                                      uint32_t addr) {
    asm volatile("ldmatrix.sync.aligned.m8n8.x4.shared.b16 {%0,%1,%2,%3}, [%4];"
                 : "=r"(r0), "=r"(r1), "=r"(r2), "=r"(r3) : "r"(addr));
}
__device__ __forceinline__ void mma16816(float* c, const uint32_t* a, const uint32_t* b) {
    asm volatile("mma.sync.aligned.m16n8k16.row.col.f32.bf16.bf16.f32 "
                 "{%0,%1,%2,%3}, {%4,%5,%6,%7}, {%8,%9}, {%0,%1,%2,%3};"
                 : "+f"(c[0]), "+f"(c[1]), "+f"(c[2]), "+f"(c[3])
                 : "r"(a[0]), "r"(a[1]), "r"(a[2]), "r"(a[3]), "r"(b[0]), "r"(b[1]));
}

// ------------------------- small kernels -------------------------
__global__ void k_style(const float* __restrict__ wl, const float* __restrict__ aw,
                        const float* __restrict__ ab) {
    int w = blockIdx.x * 8 + (threadIdx.x >> 5), lane = threadIdx.x & 31;
    int b = w >> 9, ci = w & 511;
    const float* wlp = wl + b * 512;
    const float* awp = aw + (size_t)ci * 512;
    float s = 0.f;
    #pragma unroll 4
    for (int k = lane; k < 512; k += 32) s += wlp[k] * awp[k];
    #pragma unroll
    for (int o = 16; o; o >>= 1) s += __shfl_down_sync(0xffffffffu, s, o);
    if (lane == 0) g_style[w] = s * 0.04419417382415922f + ab[ci];
}

__global__ void k_wsq(const float* __restrict__ cw) {
    int i = blockIdx.x * 256 + threadIdx.x;
    if (i < COUT * CIN) {
        const float* p = cw + (size_t)i * 9;
        float s = 0.f;
        #pragma unroll
        for (int t = 0; t < 9; t++) s += p[t] * p[t];
        g_wsq[i] = s;
    }
}

__global__ void k_dcoef() {
    int w = blockIdx.x * 8 + (threadIdx.x >> 5), lane = threadIdx.x & 31;
    int b = w >> 9, co = w & 511;
    float s = 0.f;
    #pragma unroll 4
    for (int ci = lane; ci < 512; ci += 32) {
        float st = g_style[b * 512 + ci];
        s += g_wsq[co * 512 + ci] * st * st;
    }
    #pragma unroll
    for (int o = 16; o; o >>= 1) s += __shfl_down_sync(0xffffffffu, s, o);
    if (lane == 0) g_dcoef[w] = rsqrtf(s + 1e-8f);
}

// modulate + hi/lo split + transpose to pixel-major [b][pix][ci]
__global__ void __launch_bounds__(256) k_xsplit(const float* __restrict__ x) {
    __shared__ float t[64][65];
    int b = blockIdx.z, ci0 = blockIdx.y * 64, px0 = blockIdx.x * 64;
    int tid = threadIdx.x;
    for (int e = tid; e < 4096; e += 256) {
        int ci_l = e >> 6, px = e & 63;
        t[ci_l][px] = x[(((size_t)b * 512 + ci0 + ci_l) << 10) + px0 + px]
                    * g_style[b * 512 + ci0 + ci_l];
    }
    __syncthreads();
    for (int e = tid; e < 4096; e += 256) {
        int px_l = e >> 6, ci_l = e & 63;
        float v = t[ci_l][px_l];
        __nv_bfloat16 h = __float2bfloat16(v);
        size_t d = ((size_t)(b << 10) + px0 + px_l) * 512 + ci0 + ci_l;
        g_xth[d] = h;
        g_xtl[d] = __float2bfloat16(v - __bfloat162float(h));
    }
}

// build shifted, 16B-xor-swizzled X tiles (zero padded rows/cells)
__global__ void __launch_bounds__(256) k_xbuild() {
    int s = blockIdx.z, c = blockIdx.y;
    int q = blockIdx.x * 4 + (threadIdx.x >> 6);
    int kp = threadIdx.x & 63;
    int k = kp ^ ((q & 7) << 3);
    __nv_bfloat16 h = __float2bfloat16(0.f), l = __float2bfloat16(0.f);
    if (q < NQV) {
        int b = q / 1156, r = q - b * 1156;
        int mm = r / 34 - (s >> 1), nn = r % 34 - (s & 1);
        if ((unsigned)mm < 32u && (unsigned)nn < 32u) {
            size_t si = ((size_t)(b << 10) + mm * 32 + nn) * 512 + c * 64 + k;
            h = g_xth[si]; l = g_xtl[si];
        }
    }
    size_t d = ((size_t)(s * 8 + c) * NPOSR + q) * 64 + kp;
    g_Xh[d] = h; g_Xl[d] = l;
}

// build swizzled W tiles
__global__ void __launch_bounds__(256) k_wbuild(const float* __restrict__ cw) {
    int tap = blockIdx.z, c = blockIdx.y;
    int co = blockIdx.x * 4 + (threadIdx.x >> 6);
    int kp = threadIdx.x & 63;
    int k = kp ^ ((co & 7) << 3);
    float w = cw[((size_t)co * 512 + c * 64 + k) * 9 + tap];
    __nv_bfloat16 h = __float2bfloat16(w);
    size_t d = ((size_t)(tap * 8 + c) * 512 + co) * 64 + kp;
    g_Wh[d] = h;
    g_Wl[d] = __float2bfloat16(w - __bfloat162float(h));
}

// ------------------------- GEMM (mma.sync bf16, 3-term split) -------------------------
// D[q, co] per parity p: sum over (pass, tap) K-blocks of 512, chunked by 64.
__global__ void __launch_bounds__(256) k_gemm() {
    extern __shared__ __align__(1024) char sm[];   // [2 stages][A 16KB | B 16KB]
    const int tid = threadIdx.x;
    const int p = blockIdx.z, by = blockIdx.y;
    const int qbase = blockIdx.x * 128;
    const int ntap = c_nkb[p];
    const int NKB = 3 * ntap * 8;
    const int wid = tid >> 5, lane = tid & 31;
    const int wm = wid & 1, wn = wid >> 1;         // 2 x 4 warps -> 64 x 32 per warp
    const uint32_t sbase = smem_u32(sm);

    float acc[4][4][4];
    #pragma unroll
    for (int mt = 0; mt < 4; mt++)
        #pragma unroll
        for (int nt = 0; nt < 4; nt++)
            #pragma unroll
            for (int r = 0; r < 4; r++) acc[mt][nt][r] = 0.f;

    // ldmatrix per-lane addressing (rows of 128B, 16B-xor swizzle by row&7)
    const int arow = lane & 15;
    const uint32_t acolhi = (uint32_t)(lane >> 4) << 4;
    const uint32_t asw = (uint32_t)(arow & 7) << 4;
    uint32_t aoff[4];
    #pragma unroll
    for (int mt = 0; mt < 4; mt++) aoff[mt] = (wm * 64 + mt * 16 + arow) * 128;

    const int bnl = (lane & 7) + ((lane >> 4) << 3);
    const uint32_t bhi = (uint32_t)((lane >> 3) & 1) << 4;
    const uint32_t bsw = (uint32_t)(lane & 7) << 4;
    uint32_t boff[2];
    #pragma unroll
    for (int g = 0; g < 2; g++) boff[g] = (wn * 32 + g * 16 + bnl) * 128;

    auto stage_load = [&](int s, int kb) {
        int c = kb & 7, j = kb >> 3;
        int ti = j % ntap, pass = j / ntap;
        int sh = c_shf[p][ti], tap = c_taps[p][ti];
        const char* Ag = (const char*)((pass == 1 ? g_Xl : g_Xh)
                        + ((size_t)(sh * 8 + c) * NPOSR + qbase) * 64) + tid * 16;
        const char* Bg = (const char*)((pass == 2 ? g_Wl : g_Wh)
                        + ((size_t)(tap * 8 + c) * 512 + by * 128) * 64) + tid * 16;
        uint32_t sa = sbase + s * 32768 + tid * 16;
        #pragma unroll
        for (int i = 0; i < 4; i++) {
            cp16(sa + i * 4096,         Ag + i * 4096);
            cp16(sa + 16384 + i * 4096, Bg + i * 4096);
        }
        asm volatile("cp.async.commit_group;" ::: "memory");
    };

    stage_load(0, 0);
    for (int kb = 0; kb < NKB; kb++) {
        int s = kb & 1;
        if (kb + 1 < NKB) {
            stage_load(s ^ 1, kb + 1);
            asm volatile("cp.async.wait_group 1;" ::: "memory");
        } else {
            asm volatile("cp.async.wait_group 0;" ::: "memory");
        }
        __syncthreads();

        uint32_t Abase = sbase + s * 32768;
        uint32_t Bbase = Abase + 16384;
        #pragma unroll
        for (int ks = 0; ks < 4; ks++) {
            uint32_t A[4][4], Bf[4][2];
            uint32_t ak = (((uint32_t)ks << 5) | acolhi) ^ asw;
            #pragma unroll
            for (int mt = 0; mt < 4; mt++)
                ldsm4(A[mt][0], A[mt][1], A[mt][2], A[mt][3], Abase + aoff[mt] + ak);
            uint32_t bk = (((uint32_t)ks << 5) | bhi) ^ bsw;
            #pragma unroll
            for (int g = 0; g < 2; g++)
                ldsm4(Bf[2*g][0], Bf[2*g][1], Bf[2*g+1][0], Bf[2*g+1][1], Bbase + boff[g] + bk);
            #pragma unroll
            for (int mt = 0; mt < 4; mt++)
                #pragma unroll
                for (int nt = 0; nt < 4; nt++)
                    mma16816(acc[mt][nt], A[mt], Bf[nt]);
        }
        __syncthreads();
    }

    // store: c0,c1 -> (row, co..co+1); c2,c3 -> (row+8, ...)
    #pragma unroll
    for (int mt = 0; mt < 4; mt++) {
        int r0 = qbase + wm * 64 + mt * 16 + (lane >> 2);
        #pragma unroll
        for (int nt = 0; nt < 4; nt++) {
            int co = by * 128 + wn * 32 + nt * 8 + ((lane & 3) << 1);
            if (r0 < NQV)
                *(float2*)&g_yp[IDX(p, r0) * 512 + co] = make_float2(acc[mt][nt][0], acc[mt][nt][1]);
            if (r0 + 8 < NQV)
                *(float2*)&g_yp[IDX(p, r0 + 8) * 512 + co] = make_float2(acc[mt][nt][2], acc[mt][nt][3]);
        }
    }
}

// ------------------------- FIR + demod + noise + bias + lrelu + clamp -------------------------
// y[rr, cc] (65x65) = g_yp[(rr&1)*2+(cc&1)][b*1156 + (rr>>1)*34 + (cc>>1)][co]
__global__ void __launch_bounds__(256) k_fir(const float* __restrict__ noise,
                                             const float* __restrict__ nstr,
                                             const float* __restrict__ bias,
                                             float* __restrict__ out) {
    extern __shared__ float fs[];                 // ys[5*67*32] + ob[2*64*33]
    float* ys = fs;
    float* ob = fs + 5 * 67 * 32;
    const int u0 = blockIdx.x * 2;
    const int co0 = blockIdx.y * 32;
    const int b = blockIdx.z;
    const int tid = threadIdx.x;

    for (int e = tid; e < 5 * 67 * 32; e += 256) {
        int co_l = e & 31, t = e >> 5;
        int cc = t % 67 - 1;
        int rr = t / 67 + u0 - 1;
        float v = 0.f;
        if ((unsigned)rr <= 64u && (unsigned)cc <= 64u) {
            int pp = ((rr & 1) << 1) | (cc & 1);
            int q = b * 1156 + (rr >> 1) * 34 + (cc >> 1);
            v = g_yp[IDX(pp, q) * 512 + co0 + co_l];
        }
        ys[e] = v;
    }
    __syncthreads();

    const int co_l = tid & 31, vg = tid >> 5;
    const float fw[4] = {0.25f, 0.75f, 0.75f, 0.25f};
    const float dc = g_dcoef[b * 512 + co0 + co_l];
    const float ns = nstr[0];
    const float bi = bias[co0 + co_l];

    #pragma unroll
    for (int ul = 0; ul < 2; ul++) {
        int u = u0 + ul;
        #pragma unroll
        for (int j = 0; j < 8; j++) {
            int v = vg * 8 + j;
            float accv = 0.f;
            #pragma unroll
            for (int a = 0; a < 4; a++) {
                float rsum = 0.f;
                #pragma unroll
                for (int bb = 0; bb < 4; bb++)
                    rsum = fmaf(fw[bb], ys[((ul + a) * 67 + v + bb) * 32 + co_l], rsum);
                accv = fmaf(fw[a], rsum, accv);
            }
            float val = fmaf(noise[(b << 12) + u * 64 + v], ns, accv * dc) + bi;
            val = (val > 0.f ? val : 0.2f * val) * 1.4142135623730951f;
            val = fminf(fmaxf(val, -256.f), 256.f);
            ob[(ul * 64 + v) * 33 + co_l] = val;
        }
    }
    __syncthreads();
    for (int e = tid; e < 4096; e += 256) {
        int v = e & 63, cl = (e >> 6) & 31, ul = e >> 11;
        out[(((size_t)b * 512 + co0 + cl) * 64 + u0 + ul) * 64 + v] = ob[(ul * 64 + v) * 33 + cl];
    }
}

// ------------------------- launch -------------------------
extern "C" void kernel_launch(void* const* d_in, const int* in_sizes, int n_in,
                              void* d_out, int out_size) {
    const float* x     = (const float*)d_in[0];
    const float* wl    = (const float*)d_in[1];
    const float* aw    = (const float*)d_in[2];
    const float* ab    = (const float*)d_in[3];
    const float* cw    = (const float*)d_in[4];
    const float* noise = (const float*)d_in[5];
    const float* nstr  = (const float*)d_in[6];
    const float* bias  = (const float*)d_in[7];
    float* out = (float*)d_out;

    cudaFuncSetAttribute(k_gemm, cudaFuncAttributeMaxDynamicSharedMemorySize, 65536);
    cudaFuncSetAttribute(k_fir, cudaFuncAttributeMaxDynamicSharedMemorySize,
                         (5 * 67 * 32 + 2 * 64 * 33) * 4);

    k_style<<<1024, 256>>>(wl, aw, ab);
    k_wsq<<<1024, 256>>>(cw);
    k_dcoef<<<1024, 256>>>();
    k_xsplit<<<dim3(16, 8, B_), 256>>>(x);
    k_wbuild<<<dim3(128, 8, 9), 256>>>(cw);
    k_xbuild<<<dim3(NPOSR / 4, 8, 4), 256>>>();

    k_gemm<<<dim3(146, 4, 4), 256, 65536>>>();
    k_fir<<<dim3(32, 16, B_), 256, (5 * 67 * 32 + 2 * 64 * 33) * 4>>>(noise, nstr, bias, out);
}